// round 1
// baseline (speedup 1.0000x reference)
#include <cuda_runtime.h>

// VQ nearest-codebook quantization.
// x: (B=16, D=64, H=64, W=64) f32, codebook: (K=1024, D=64) f32.
// Out: quantized (B, D, H, W) f32 [4194304 elems] then indices as f32 (B,H,W) [65536 elems].
//
// Block = one (b, h) pair -> 64 points (all w). K looped in chunks of 128 in smem.
// Fused distance + argmin (d2 = ||c||^2 - 2 x.c ; ||x||^2 omitted, constant per point).

#define TM 64      // points per block (the w dimension)
#define TK 128     // codebook chunk in smem
#define DD 64      // feature dim
#define KTOT 1024
#define NTHREADS 256

// smem layout (floats):
//  ps : [TM][DD+1]   = 64*65  = 4160
//  cs : [TK][DD+1]   = 128*65 = 8320
//  cn : [TK]         = 128
#define PS_STRIDE 65
#define CS_STRIDE 65
#define SMEM_FLOATS (TM * PS_STRIDE + TK * CS_STRIDE + TK)

__global__ void __launch_bounds__(NTHREADS, 1)
vq_kernel(const float* __restrict__ x, const float* __restrict__ cb,
          float* __restrict__ out, int write_idx) {
    extern __shared__ float smem[];
    float* ps = smem;                       // [TM][65]
    float* cs = smem + TM * PS_STRIDE;      // [TK][65]
    float* cn = cs + TK * CS_STRIDE;        // [TK]

    const int tid = threadIdx.x;
    const int bh = blockIdx.x;              // 0..1023
    const int b = bh >> 6;
    const int h = bh & 63;

    // x[b][d][h][w] = x + b*262144 + d*4096 + h*64 + w
    const float* xbase = x + (size_t)b * (DD * 64 * 64) + (size_t)h * 64;

    // Load point tile: ps[w][d] = x[b][d][h][w]. Coalesced on gmem (w contiguous).
    for (int i = tid; i < TM * DD; i += NTHREADS) {
        int d = i >> 6;
        int w = i & 63;
        ps[w * PS_STRIDE + d] = xbase[(size_t)d * 4096 + w];
    }

    // Register tile: 4 points x 8 codewords per thread.
    const int ty = tid >> 4;   // 0..15 -> points ty*4 .. ty*4+3
    const int tx = tid & 15;   // 0..15 -> codewords tx + 16*j, j=0..7

    float bestv[4];
    int   besti[4];
#pragma unroll
    for (int i = 0; i < 4; i++) { bestv[i] = 3.4e38f; besti[i] = 0; }

    for (int chunk = 0; chunk < KTOT; chunk += TK) {
        __syncthreads();  // previous iteration done reading cs/cn
        // Load codebook chunk (coalesced), conflict-free smem write.
        for (int i = tid; i < TK * DD; i += NTHREADS) {
            int c = i >> 6;
            int d = i & 63;
            cs[c * CS_STRIDE + d] = cb[(size_t)(chunk + c) * DD + d];
        }
        __syncthreads();
        // Codeword norms.
        if (tid < TK) {
            float s = 0.f;
#pragma unroll
            for (int d = 0; d < DD; d++) {
                float v = cs[tid * CS_STRIDE + d];
                s += v * v;
            }
            cn[tid] = s;
        }
        __syncthreads();

        float acc[4][8];
#pragma unroll
        for (int i = 0; i < 4; i++)
#pragma unroll
            for (int j = 0; j < 8; j++) acc[i][j] = 0.f;

#pragma unroll 8
        for (int d = 0; d < DD; d++) {
            float a0 = ps[(ty * 4 + 0) * PS_STRIDE + d];
            float a1 = ps[(ty * 4 + 1) * PS_STRIDE + d];
            float a2 = ps[(ty * 4 + 2) * PS_STRIDE + d];
            float a3 = ps[(ty * 4 + 3) * PS_STRIDE + d];
            float bb[8];
#pragma unroll
            for (int j = 0; j < 8; j++) bb[j] = cs[(tx + 16 * j) * CS_STRIDE + d];
#pragma unroll
            for (int j = 0; j < 8; j++) {
                acc[0][j] += a0 * bb[j];
                acc[1][j] += a1 * bb[j];
                acc[2][j] += a2 * bb[j];
                acc[3][j] += a3 * bb[j];
            }
        }

        // Update running argmin (first-occurrence tie-break, like jnp.argmin).
#pragma unroll
        for (int j = 0; j < 8; j++) {
            int c = chunk + tx + 16 * j;
            float nrm = cn[tx + 16 * j];
#pragma unroll
            for (int i = 0; i < 4; i++) {
                float d2 = fmaf(-2.f, acc[i][j], nrm);
                if (d2 < bestv[i] || (d2 == bestv[i] && c < besti[i])) {
                    bestv[i] = d2;
                    besti[i] = c;
                }
            }
        }
    }

    // Reduce argmin across the 16 tx-lanes (width-16 butterfly in the warp).
#pragma unroll
    for (int off = 8; off > 0; off >>= 1) {
#pragma unroll
        for (int i = 0; i < 4; i++) {
            float v2 = __shfl_down_sync(0xFFFFFFFFu, bestv[i], off, 16);
            int   c2 = __shfl_down_sync(0xFFFFFFFFu, besti[i], off, 16);
            if (v2 < bestv[i] || (v2 == bestv[i] && c2 < besti[i])) {
                bestv[i] = v2;
                besti[i] = c2;
            }
        }
    }

    __syncthreads();  // everyone done with ps/cs before reuse
    int* bidx = (int*)smem;  // reuse, 64 ints
    if (tx == 0) {
#pragma unroll
        for (int i = 0; i < 4; i++) bidx[ty * 4 + i] = besti[i];
    }
    __syncthreads();

    // Gather winning codebook rows coalesced into smem, then write transposed.
    float* tmp = smem + 128;  // [TM][65] staging (after the 64 idx ints, plenty of room)
    for (int i = tid; i < TM * DD; i += NTHREADS) {
        int w = i >> 6;
        int d = i & 63;
        tmp[w * PS_STRIDE + d] = cb[(size_t)bidx[w] * DD + d];
    }
    __syncthreads();
    // quantized[b][d][h][w]
    float* qbase = out + (size_t)b * (DD * 64 * 64) + (size_t)h * 64;
    for (int i = tid; i < TM * DD; i += NTHREADS) {
        int d = i >> 6;
        int w = i & 63;
        qbase[(size_t)d * 4096 + w] = tmp[w * PS_STRIDE + d];
    }

    if (write_idx && tid < TM) {
        // indices as float32 after the 4194304 quantized elements
        out[(size_t)16 * 64 * 64 * 64 + (size_t)b * 4096 + (size_t)h * 64 + tid] =
            (float)bidx[tid];
    }
}

extern "C" void kernel_launch(void* const* d_in, const int* in_sizes, int n_in,
                              void* d_out, int out_size) {
    // x has 4194304 elements, codebook 65536 — identify defensively.
    const float* x  = (const float*)d_in[0];
    const float* cb = (const float*)d_in[1];
    if (n_in >= 2 && in_sizes[0] == 1024 * 64 && in_sizes[1] == 16 * 64 * 64 * 64) {
        x  = (const float*)d_in[1];
        cb = (const float*)d_in[0];
    }
    float* out = (float*)d_out;

    const int smem_bytes = SMEM_FLOATS * (int)sizeof(float);
    cudaFuncSetAttribute(vq_kernel, cudaFuncAttributeMaxDynamicSharedMemorySize,
                         smem_bytes);

    int write_idx = (out_size >= 16 * 64 * 64 * 64 + 16 * 64 * 64) ? 1 : 0;
    vq_kernel<<<1024, NTHREADS, smem_bytes>>>(x, cb, out, write_idx);
}

// round 2
// speedup vs baseline: 1.4068x; 1.4068x over previous
#include <cuda_runtime.h>

// VQ nearest-codebook quantization, fp32-exact, fused distance+argmin.
// x: (B=16, D=64, H=64, W=64) f32, codebook: (K=1024, D=64) f32.
// Out: quantized (B,D,H,W) f32 [4194304] then indices as f32 (B,H,W) [65536].

#define TM 64      // points per block (the w dimension of one (b,h))
#define TK 128     // codebook chunk resident in smem
#define DD 64      // feature dim
#define KTOT 1024
#define NTHREADS 256

// float4-friendly padded strides (68 % 4 == 0; bank pattern 4*tx mod 32 is
// conflict-free per 8-lane LDS.128 phase)
#define PS_STRIDE 68
#define CS_STRIDE 68
#define SMEM_FLOATS (TM * PS_STRIDE + TK * CS_STRIDE)

__device__ float g_cnorm[KTOT];

__global__ void norm_kernel(const float* __restrict__ cb) {
    int k = blockIdx.x * blockDim.x + threadIdx.x;
    if (k < KTOT) {
        const float4* row = (const float4*)(cb + (size_t)k * DD);
        float s = 0.f;
#pragma unroll
        for (int i = 0; i < DD / 4; i++) {
            float4 v = row[i];
            s += v.x * v.x + v.y * v.y + v.z * v.z + v.w * v.w;
        }
        g_cnorm[k] = s;
    }
}

__global__ void __launch_bounds__(NTHREADS, 2)
vq_kernel(const float* __restrict__ x, const float* __restrict__ cb,
          float* __restrict__ out, int write_idx) {
    extern __shared__ float smem[];
    float* ps = smem;                       // [TM][68]
    float* cs = smem + TM * PS_STRIDE;      // [TK][68]

    const int tid = threadIdx.x;
    const int bh = blockIdx.x;              // 0..1023
    const int b = bh >> 6;
    const int h = bh & 63;

    // x[b][d][h][w]
    const float* xbase = x + (size_t)b * (DD * 64 * 64) + (size_t)h * 64;

    // Point tile: ps[w][d] = x[b][d][h][w]. float4 gmem loads (w contiguous),
    // scalar transposed smem stores (one-time cost).
    for (int i = tid; i < TM * DD / 4; i += NTHREADS) {
        int d  = i >> 4;        // 0..63
        int w4 = (i & 15) * 4;  // 0,4,...,60
        float4 v = *(const float4*)(xbase + (size_t)d * 4096 + w4);
        ps[(w4 + 0) * PS_STRIDE + d] = v.x;
        ps[(w4 + 1) * PS_STRIDE + d] = v.y;
        ps[(w4 + 2) * PS_STRIDE + d] = v.z;
        ps[(w4 + 3) * PS_STRIDE + d] = v.w;
    }

    // Register tile: 4 points x 8 codewords per thread.
    const int ty = tid >> 4;   // 0..15 -> points ty*4 .. ty*4+3
    const int tx = tid & 15;   // 0..15 -> codewords tx + 16*j, j=0..7

    float bestv[4];
    int   besti[4];
#pragma unroll
    for (int i = 0; i < 4; i++) { bestv[i] = 3.4e38f; besti[i] = 0; }

    const float* ps0 = ps + (ty * 4 + 0) * PS_STRIDE;
    const float* ps1 = ps + (ty * 4 + 1) * PS_STRIDE;
    const float* ps2 = ps + (ty * 4 + 2) * PS_STRIDE;
    const float* ps3 = ps + (ty * 4 + 3) * PS_STRIDE;

    for (int chunk = 0; chunk < KTOT; chunk += TK) {
        __syncthreads();  // previous iteration done reading cs
        // Codebook chunk: float4 both sides (cb row-major, 16B aligned).
        for (int i = tid; i < TK * DD / 4; i += NTHREADS) {
            int c  = i >> 4;        // 0..127
            int d4 = (i & 15) * 4;  // 0..60
            *(float4*)(cs + c * CS_STRIDE + d4) =
                *(const float4*)(cb + (size_t)(chunk + c) * DD + d4);
        }
        __syncthreads();

        float acc[4][8];
#pragma unroll
        for (int i = 0; i < 4; i++)
#pragma unroll
            for (int j = 0; j < 8; j++) acc[i][j] = 0.f;

#pragma unroll 4
        for (int d4 = 0; d4 < DD / 4; d4++) {
            const int d = d4 * 4;
            float4 a0 = *(const float4*)(ps0 + d);
            float4 a1 = *(const float4*)(ps1 + d);
            float4 a2 = *(const float4*)(ps2 + d);
            float4 a3 = *(const float4*)(ps3 + d);
#pragma unroll
            for (int j = 0; j < 8; j++) {
                float4 bj = *(const float4*)(cs + (tx + 16 * j) * CS_STRIDE + d);
                acc[0][j] = fmaf(a0.x, bj.x, fmaf(a0.y, bj.y, fmaf(a0.z, bj.z, fmaf(a0.w, bj.w, acc[0][j]))));
                acc[1][j] = fmaf(a1.x, bj.x, fmaf(a1.y, bj.y, fmaf(a1.z, bj.z, fmaf(a1.w, bj.w, acc[1][j]))));
                acc[2][j] = fmaf(a2.x, bj.x, fmaf(a2.y, bj.y, fmaf(a2.z, bj.z, fmaf(a2.w, bj.w, acc[2][j]))));
                acc[3][j] = fmaf(a3.x, bj.x, fmaf(a3.y, bj.y, fmaf(a3.z, bj.z, fmaf(a3.w, bj.w, acc[3][j]))));
            }
        }

        // Running argmin (ascending c order; first-occurrence tie-break).
#pragma unroll
        for (int j = 0; j < 8; j++) {
            int c = chunk + tx + 16 * j;
            float nrm = __ldg(&g_cnorm[c]);
#pragma unroll
            for (int i = 0; i < 4; i++) {
                float d2 = fmaf(-2.f, acc[i][j], nrm);
                if (d2 < bestv[i] || (d2 == bestv[i] && c < besti[i])) {
                    bestv[i] = d2;
                    besti[i] = c;
                }
            }
        }
    }

    // Reduce argmin across the 16 tx-lanes (width-16 butterfly).
#pragma unroll
    for (int off = 8; off > 0; off >>= 1) {
#pragma unroll
        for (int i = 0; i < 4; i++) {
            float v2 = __shfl_down_sync(0xFFFFFFFFu, bestv[i], off, 16);
            int   c2 = __shfl_down_sync(0xFFFFFFFFu, besti[i], off, 16);
            if (v2 < bestv[i] || (v2 == bestv[i] && c2 < besti[i])) {
                bestv[i] = v2;
                besti[i] = c2;
            }
        }
    }

    __syncthreads();  // everyone done with ps/cs before reuse
    int* bidx = (int*)smem;  // 64 ints
    if (tx == 0) {
#pragma unroll
        for (int i = 0; i < 4; i++) bidx[ty * 4 + i] = besti[i];
    }
    __syncthreads();

    // Gather winning codebook rows coalesced into smem, then write transposed.
    float* tmp = smem + 128;  // [TM][68] staging
    for (int i = tid; i < TM * DD / 4; i += NTHREADS) {
        int w  = i >> 4;
        int d4 = (i & 15) * 4;
        *(float4*)(tmp + w * PS_STRIDE + d4) =
            *(const float4*)(cb + (size_t)bidx[w] * DD + d4);
    }
    __syncthreads();
    float* qbase = out + (size_t)b * (DD * 64 * 64) + (size_t)h * 64;
    for (int i = tid; i < TM * DD / 4; i += NTHREADS) {
        int d  = i >> 4;
        int w4 = (i & 15) * 4;
        float4 v;
        v.x = tmp[(w4 + 0) * PS_STRIDE + d];
        v.y = tmp[(w4 + 1) * PS_STRIDE + d];
        v.z = tmp[(w4 + 2) * PS_STRIDE + d];
        v.w = tmp[(w4 + 3) * PS_STRIDE + d];
        *(float4*)(qbase + (size_t)d * 4096 + w4) = v;
    }

    if (write_idx && tid < TM) {
        out[(size_t)16 * 64 * 64 * 64 + (size_t)b * 4096 + (size_t)h * 64 + tid] =
            (float)bidx[tid];
    }
}

extern "C" void kernel_launch(void* const* d_in, const int* in_sizes, int n_in,
                              void* d_out, int out_size) {
    const float* x  = (const float*)d_in[0];
    const float* cb = (const float*)d_in[1];
    if (n_in >= 2 && in_sizes[0] == 1024 * 64 && in_sizes[1] == 16 * 64 * 64 * 64) {
        x  = (const float*)d_in[1];
        cb = (const float*)d_in[0];
    }
    float* out = (float*)d_out;

    const int smem_bytes = SMEM_FLOATS * (int)sizeof(float);
    static int configured = 0;
    cudaFuncSetAttribute(vq_kernel, cudaFuncAttributeMaxDynamicSharedMemorySize,
                         smem_bytes);
    (void)configured;

    norm_kernel<<<(KTOT + 255) / 256, 256>>>(cb);
    int write_idx = (out_size >= 16 * 64 * 64 * 64 + 16 * 64 * 64) ? 1 : 0;
    vq_kernel<<<1024, NTHREADS, smem_bytes>>>(x, cb, out, write_idx);
}